// round 17
// baseline (speedup 1.0000x reference)
#include <cuda_runtime.h>
#include <cuda_bf16.h>
#include <cuda_fp16.h>
#include <math.h>
#include <stdint.h>

#define B_TOT   32768
#define OWN_DIM 3
#define N_INTR  32
#define INT_DIM 7
#define D       128
#define OBS_DIM 227
#define HID     256

#define R1      32
#define NTILES  (B_TOT / R1)
#define R2      128
#define X_STR   260
#define NT1     1024
#define NT2     512

#define ASTR    272
#define TILE_BYTES (128 * ASTR)

#define BY_AHI    1024
#define BY_ALO    (BY_AHI + TILE_BYTES)
#define BY_BHI    (BY_ALO + TILE_BYTES)
#define BY_BLO    (BY_BHI + TILE_BYTES)
#define BY_F32    (BY_BLO + TILE_BYTES)
#define F_OBS   (BY_F32 / 4)
#define F_OWNE  (F_OBS  + R1 * OBS_DIM)
#define F_Q     (F_OWNE + R1 * D)
#define F_SC    (F_Q    + R1 * D)
#define F_AL    (F_SC   + R1 * N_INTR)
#define F_INTW  (F_AL   + R1 * N_INTR)
#define F_OWNW  (F_INTW + INT_DIM * D)
#define F_INTB  (F_OWNW + OWN_DIM * D)
#define F_VATT  (F_INTB + D)
#define F_MAP   (F_VATT + D)
#define F_WS    (F_MAP + R1 * N_INTR)
#define F_NC    (F_WS + 32)
#define SMEM1_BYTES ((F_NC + 1) * 4)

#define XSTRB   144
#define XCH     (R2 * XSTRB)
#define M_XH    0
#define M_XL    (4 * XCH)
#define M_W0    (8 * XCH)
#define WBUF    36864
#define SMEM2_BYTES (M_W0 + 2 * WBUF)

__device__ uint32_t gWkF[8704];
__device__ uint32_t gWqF[8704];
__device__ uint32_t gWvpF[8704];
__device__ uint32_t gW1F[4][9216];
__device__ uint32_t gW2F[4][9216];
__device__ __half g_xh[(size_t)B_TOT * 256];
__device__ __half g_xl[(size_t)B_TOT * 256];

typedef unsigned long long u64;

__device__ __forceinline__ float lrelu(float x) { return fmaxf(x, 0.2f * x); }
__device__ __forceinline__ float tanh_ap(float x) {
    float y; asm("tanh.approx.f32 %0, %1;" : "=f"(y) : "f"(x)); return y;
}
__device__ __forceinline__ uint32_t smem_u32(const void* p) {
    uint32_t a;
    asm("{ .reg .u64 t; cvta.to.shared.u64 t, %1; cvt.u32.u64 %0, t; }" : "=r"(a) : "l"(p));
    return a;
}
__device__ __forceinline__ uint32_t f16pair(float a, float b) {
    __half2 t = __floats2half2_rn(a, b);
    return *(uint32_t*)&t;
}

#define LDSM_X4(r0, r1, r2, r3, addr) \
    asm volatile("ldmatrix.sync.aligned.m8n8.x4.shared.b16 {%0,%1,%2,%3}, [%4];" \
                 : "=r"(r0), "=r"(r1), "=r"(r2), "=r"(r3) : "r"(addr))

__device__ __forceinline__ void mma_f16(float* c, const uint32_t* a, const uint32_t* b) {
    asm volatile(
        "mma.sync.aligned.m16n8k16.row.col.f32.f16.f16.f32 "
        "{%0,%1,%2,%3}, {%4,%5,%6,%7}, {%8,%9}, {%0,%1,%2,%3};"
        : "+f"(c[0]), "+f"(c[1]), "+f"(c[2]), "+f"(c[3])
        : "r"(a[0]), "r"(a[1]), "r"(a[2]), "r"(a[3]), "r"(b[0]), "r"(b[1]));
}

#define GROUP_BAR256(id) \
    asm volatile("bar.sync %0, 256;" :: "r"(id) : "memory")
#define CP_ASYNC16(dst, src) \
    asm volatile("cp.async.ca.shared.global [%0], [%1], 16;" :: "r"(dst), "l"(src))
#define CP_COMMIT() asm volatile("cp.async.commit_group;" ::: "memory")
#define CP_WAIT0()  asm volatile("cp.async.wait_group 0;" ::: "memory")

// =====================================================================
// Prep (unchanged from R16)
// =====================================================================
__global__ void __launch_bounds__(256, 4)
k_prep(const float* __restrict__ Wk, const float* __restrict__ W1,
       const float* __restrict__ W2, const float* __restrict__ Wq,
       const float* __restrict__ Wv, const float* __restrict__ projW)
{
    int idx = blockIdx.x * 256 + threadIdx.x;
    if (idx < 2 * 8192) {
        const float* W = (idx < 8192) ? Wk : Wq;
        uint32_t* IF = (idx < 8192) ? gWkF : gWqF;
        int j = idx & 8191;
        int ep = j >> 7, n = j & 127;
        int e0 = 2 * ep;
        IF[n * 68 + ep] = f16pair(W[e0 * D + n], W[(e0 + 1) * D + n]);
    } else if (idx < 2 * 8192 + 2 * 32768) {
        int j = idx - 2 * 8192;
        const float* W = (j < 32768) ? W1 : W2;
        uint32_t* WF = (j < 32768) ? &gW1F[0][0] : &gW2F[0][0];
        j &= 32767;
        int kk = j >> 13, r = j & 8191;
        int n = r & 255, kp = r >> 8;
        int k0 = kk * 64 + 2 * kp;
        WF[kk * 9216 + n * 36 + kp] =
            f16pair(W[(size_t)k0 * HID + n], W[(size_t)(k0 + 1) * HID + n]);
    } else if (idx < 2 * 8192 + 2 * 32768 + 8192) {
        int j = idx - (2 * 8192 + 2 * 32768);
        int n = j & 127, f0 = 2 * (j >> 7);
        float s0 = 0.f, s1 = 0.f;
        #pragma unroll 4
        for (int e = 0; e < D; e++) {
            float pc = projW[e * D + n];
            s0 += Wv[f0 * D + e] * pc;
            s1 += Wv[(f0 + 1) * D + e] * pc;
        }
        gWvpF[n * 68 + (f0 >> 1)] = f16pair(s0, s1);
    }
}

// =====================================================================
// Kernel 1: attention, PERSISTENT tiles; Wk resident; Wq/WvProj cp.async
// =====================================================================
__global__ void __launch_bounds__(NT1, 1)
k_attn(const float* __restrict__ obs,
       const float* __restrict__ ownW, const float* __restrict__ ownB,
       const float* __restrict__ intW, const float* __restrict__ intB,
       const float* __restrict__ vatt, const float* __restrict__ projB)
{
    extern __shared__ float sm[];
    char* smc = (char*)sm;
    const uint32_t smb = smem_u32(sm);

    float* sObs  = sm + F_OBS;
    float* sWsum = sm + F_OWNE;
    float* sQ    = sm + F_Q;
    float* sSc   = sm + F_SC;
    float* sAl   = sm + F_AL;
    float* sIntW = sm + F_INTW;
    float* sOwnW = sm + F_OWNW;
    float* sIntB = sm + F_INTB;
    float* sVatt = sm + F_VATT;
    int*   sMap  = (int*)(sm + F_MAP);
    int*   sWs   = (int*)(sm + F_WS);
    int*   sNC   = (int*)(sm + F_NC);

    const int tid  = threadIdx.x;
    const int wid  = tid >> 5;
    const int lane = tid & 31;
    const float NEG_INF = __int_as_float(0xff800000u);

    const int wr = wid >> 3, wc = wid & 7;
    const int lt = lane >> 3, lw = lane & 7;
    const uint32_t aoff = (uint32_t)(((lt & 1) * 8 + lw) * ASTR + (lt >> 1) * 16);
    const uint32_t boff = (uint32_t)((((lt >> 1) * 8 + lw) + 16 * wc) * ASTR + (lt & 1) * 16);
    const uint32_t aBase0 = smb + BY_AHI + (uint32_t)(32 * wr) * ASTR + aoff;
    const uint32_t aBase1 = aBase0 + 16 * ASTR;
    const uint32_t alBase0 = aBase0 + TILE_BYTES;
    const uint32_t alBase1 = aBase1 + TILE_BYTES;
    const uint32_t bQ0 = smb + BY_BHI + boff;   // Wq / WvProj (alternating)
    const uint32_t bK0 = smb + BY_BLO + boff;   // Wk (resident)
    const uint32_t aQ0 = smb + BY_AHI + aoff;
    const uint32_t aQ1 = aQ0 + 16 * ASTR;
    const uint32_t aQl0 = aQ0 + TILE_BYTES;
    const uint32_t aQl1 = aQ1 + TILE_BYTES;

    // ---- CTA-invariant staging ----
    for (int i = tid; i < INT_DIM * D; i += NT1)  sIntW[i] = intW[i];
    if (tid < OWN_DIM * D) sOwnW[tid] = ownW[tid];
    if (tid < D) { sIntB[tid] = intB[tid]; sVatt[tid] = vatt[tid]; }
    // Wk image -> BLO (resident forever); Wq image -> BHI for first tile
    for (int i = tid; i < 2176; i += NT1)
        CP_ASYNC16(smb + BY_BLO + (uint32_t)i * 16, (const void*)(((const uint4*)gWkF) + i));
    CP_COMMIT();
    for (int i = tid; i < 2176; i += NT1)
        CP_ASYNC16(smb + BY_BHI + (uint32_t)i * 16, (const void*)(((const uint4*)gWqF) + i));
    CP_COMMIT();

    const int gt = tid & 255;
    const int qd = 4 * (gt & 31);

    for (int tile = blockIdx.x; tile < NTILES; tile += gridDim.x) {
        const int b0 = tile * R1;

        // ---- phase 1: obs staging (also separated from prev tile by its tail sync) ----
        for (int i = tid; i < R1 * OBS_DIM; i += NT1)
            sObs[i] = obs[(size_t)b0 * OBS_DIM + i];
        __syncthreads();

        // ---- phase 2: own_e -> A image + g_x; pad mask ----
        for (int i = tid; i < R1 * D; i += NT1) {
            int r = i >> 7, d = i & 127;
            const float* o = &sObs[r * OBS_DIM];
            float a = ownB[d] + o[0] * sOwnW[d] + o[1] * sOwnW[D + d] + o[2] * sOwnW[2 * D + d];
            a = lrelu(a);
            __half h = __float2half_rn(a);
            float hf = __half2float(h);
            __half l = __float2half_rn(a - hf);
            uint32_t off = (uint32_t)r * ASTR + (uint32_t)d * 2;
            *(__half*)(smc + BY_AHI + off) = h;
            *(__half*)(smc + BY_ALO + off) = l;
            size_t gi = (size_t)(b0 + r) * 256 + d;
            g_xh[gi] = h;
            g_xl[gi] = l;
        }
        {
            int r = tid >> 5, n = tid & 31;
            const float* p = &sObs[r * OBS_DIM + OWN_DIM + n * INT_DIM];
            float s = 0.f;
            #pragma unroll
            for (int j = 0; j < INT_DIM; j++) s += fabsf(p[j]);
            sSc[tid] = (s < 1e-6f) ? NEG_INF : 0.f;
        }
        CP_WAIT0();          // Wq (+Wk on first tile) landed
        __syncthreads();

        // ---- phase 3: q = own_e @ Wq (warps 0-7, B=BHI) ----
        if (wid < 8) {
            float c[2][2][4];
            #pragma unroll
            for (int mi = 0; mi < 2; mi++)
            #pragma unroll
            for (int ni = 0; ni < 2; ni++)
            #pragma unroll
            for (int j = 0; j < 4; j++) c[mi][ni][j] = 0.f;

            #pragma unroll
            for (int kk = 0; kk < 8; kk++) {
                const uint32_t ko = kk * 32;
                uint32_t ah[2][4], al[2][4], bh[4];
                LDSM_X4(ah[0][0], ah[0][1], ah[0][2], ah[0][3], aQ0 + ko);
                LDSM_X4(ah[1][0], ah[1][1], ah[1][2], ah[1][3], aQ1 + ko);
                LDSM_X4(al[0][0], al[0][1], al[0][2], al[0][3], aQl0 + ko);
                LDSM_X4(al[1][0], al[1][1], al[1][2], al[1][3], aQl1 + ko);
                LDSM_X4(bh[0], bh[1], bh[2], bh[3], bQ0 + ko);
                #pragma unroll
                for (int mi = 0; mi < 2; mi++)
                #pragma unroll
                for (int ni = 0; ni < 2; ni++) {
                    mma_f16(c[mi][ni], ah[mi], &bh[ni * 2]);
                    mma_f16(c[mi][ni], al[mi], &bh[ni * 2]);
                }
            }
            #pragma unroll
            for (int mi = 0; mi < 2; mi++)
            #pragma unroll
            for (int ci = 0; ci < 2; ci++) {
                int row = 16 * mi + 8 * ci + (lane >> 2);
                #pragma unroll
                for (int ni = 0; ni < 2; ni++) {
                    int col = 16 * wc + 8 * ni + 2 * (lane & 3);
                    sQ[row * D + col]     = c[mi][ni][2 * ci];
                    sQ[row * D + col + 1] = c[mi][ni][2 * ci + 1];
                }
            }
        }
        __syncthreads();

        // ---- phase 4: compaction ----
        {
            int flag = (sSc[tid] == 0.f) ? 1 : 0;
            unsigned bal = __ballot_sync(0xffffffffu, flag);
            int wpos = __popc(bal & ((1u << lane) - 1));
            if (lane == 0) sWs[wid] = __popc(bal);
            __syncthreads();
            if (tid == 0) {
                int acc = 0;
                for (int w = 0; w < 32; w++) { int t = sWs[w]; sWs[w] = acc; acc += t; }
                *sNC = acc;
            }
            __syncthreads();
            if (flag) sMap[sWs[wid] + wpos] = tid;
        }
        __syncthreads();

        // WvProj copy into BHI, overlapped with the chunk loop
        for (int i = tid; i < 2176; i += NT1)
            CP_ASYNC16(smb + BY_BHI + (uint32_t)i * 16, (const void*)(((const uint4*)gWvpF) + i));
        CP_COMMIT();

        const int n_comp = *sNC;
        const int nch = (n_comp + 127) >> 7;

        // ================= chunk loop (B = BLO, resident) =================
        for (int cc = 0; cc < nch; cc++) {
            float4 wjv[INT_DIM];
            #pragma unroll
            for (int j = 0; j < INT_DIM; j++) wjv[j] = *(const float4*)&sIntW[j * D + qd];
            const float4 bbv = *(const float4*)&sIntB[qd];

            for (int it = gt; it < 32 * 32; it += 256) {
                int row = 32 * wr + (it >> 5);
                int g = cc * 128 + row;
                uint32_t off = (uint32_t)row * ASTR + (uint32_t)qd * 2;
                if (g < n_comp) {
                    int pr = sMap[g];
                    const float* p = &sObs[(pr >> 5) * OBS_DIM + OWN_DIM + (pr & 31) * INT_DIM];
                    float4 acc = bbv;
                    #pragma unroll
                    for (int j = 0; j < INT_DIM; j++) {
                        float pj = p[j];
                        acc.x += pj * wjv[j].x; acc.y += pj * wjv[j].y;
                        acc.z += pj * wjv[j].z; acc.w += pj * wjv[j].w;
                    }
                    float v0 = lrelu(acc.x), v1 = lrelu(acc.y);
                    float v2 = lrelu(acc.z), v3 = lrelu(acc.w);
                    float h0 = __half2float(__float2half_rn(v0));
                    float h1 = __half2float(__float2half_rn(v1));
                    float h2 = __half2float(__float2half_rn(v2));
                    float h3 = __half2float(__float2half_rn(v3));
                    *(uint2*)(smc + BY_AHI + off) =
                        make_uint2(f16pair(h0, h1), f16pair(h2, h3));
                    *(uint2*)(smc + BY_ALO + off) =
                        make_uint2(f16pair(v0 - h0, v1 - h1), f16pair(v2 - h2, v3 - h3));
                } else {
                    *(uint2*)(smc + BY_AHI + off) = make_uint2(0u, 0u);
                    *(uint2*)(smc + BY_ALO + off) = make_uint2(0u, 0u);
                }
            }
            GROUP_BAR256(wr + 1);

            if (cc * 128 + 32 * wr < n_comp) {
                float c[2][2][4];
                #pragma unroll
                for (int mi = 0; mi < 2; mi++)
                #pragma unroll
                for (int ni = 0; ni < 2; ni++)
                #pragma unroll
                for (int j = 0; j < 4; j++) c[mi][ni][j] = 0.f;

                #pragma unroll
                for (int kk = 0; kk < 8; kk++) {
                    const uint32_t ko = kk * 32;
                    uint32_t ah[2][4], al[2][4], bh[4];
                    LDSM_X4(ah[0][0], ah[0][1], ah[0][2], ah[0][3], aBase0 + ko);
                    LDSM_X4(ah[1][0], ah[1][1], ah[1][2], ah[1][3], aBase1 + ko);
                    LDSM_X4(al[0][0], al[0][1], al[0][2], al[0][3], alBase0 + ko);
                    LDSM_X4(al[1][0], al[1][1], al[1][2], al[1][3], alBase1 + ko);
                    LDSM_X4(bh[0], bh[1], bh[2], bh[3], bK0 + ko);
                    #pragma unroll
                    for (int mi = 0; mi < 2; mi++)
                    #pragma unroll
                    for (int ni = 0; ni < 2; ni++) {
                        mma_f16(c[mi][ni], ah[mi], &bh[ni * 2]);
                        mma_f16(c[mi][ni], al[mi], &bh[ni * 2]);
                    }
                }

                float2 vv[2];
                #pragma unroll
                for (int ni = 0; ni < 2; ni++)
                    vv[ni] = ((const float2*)sVatt)[8 * wc + 4 * ni + (lane & 3)];
                #pragma unroll
                for (int mi = 0; mi < 2; mi++)
                #pragma unroll
                for (int ci = 0; ci < 2; ci++) {
                    int crow = 32 * wr + 16 * mi + 8 * ci + (lane >> 2);
                    int g = cc * 128 + crow;
                    bool ok = (g < n_comp);
                    int pr = ok ? sMap[g] : 0;
                    const float2* qr2 = (const float2*)&sQ[(pr >> 5) * D];
                    float s = 0.f;
                    #pragma unroll
                    for (int ni = 0; ni < 2; ni++) {
                        float2 qv = qr2[8 * wc + 4 * ni + (lane & 3)];
                        s += tanh_ap(qv.x + c[mi][ni][2 * ci])     * vv[ni].x;
                        s += tanh_ap(qv.y + c[mi][ni][2 * ci + 1]) * vv[ni].y;
                    }
                    s += __shfl_xor_sync(0xffffffffu, s, 1);
                    s += __shfl_xor_sync(0xffffffffu, s, 2);
                    if (ok && (lane & 3) == 0) atomicAdd(&sSc[pr], s);
                }
            }
            GROUP_BAR256(wr + 1);
        }
        __syncthreads();

        // ---- softmax ----
        {
            int r = wid;
            float s = sSc[r * N_INTR + lane];
            float m = s;
            #pragma unroll
            for (int o = 16; o > 0; o >>= 1) m = fmaxf(m, __shfl_xor_sync(0xffffffffu, m, o));
            float e = (m == NEG_INF) ? 0.f : __expf(s - m);
            float sum = e;
            #pragma unroll
            for (int o = 16; o > 0; o >>= 1) sum += __shfl_xor_sync(0xffffffffu, sum, o);
            sAl[r * N_INTR + lane] = (sum > 0.f) ? (e / sum) : 0.f;
        }
        __syncthreads();

        // ---- wsum = alpha @ int_e ----
        {
            int r = wid;
            float wIW[INT_DIM][4];
            float wB[4];
            #pragma unroll
            for (int cq = 0; cq < 4; cq++) {
                wB[cq] = sIntB[4 * lane + cq];
                #pragma unroll
                for (int j = 0; j < INT_DIM; j++) wIW[j][cq] = sIntW[j * D + 4 * lane + cq];
            }
            float ws[4] = {0.f,0.f,0.f,0.f};
            for (int n = 0; n < N_INTR; n++) {
                float al = sAl[r * N_INTR + n];
                if (al != 0.f) {
                    const float* p = &sObs[r * OBS_DIM + OWN_DIM + n * INT_DIM];
                    float pj[INT_DIM];
                    #pragma unroll
                    for (int j = 0; j < INT_DIM; j++) pj[j] = p[j];
                    #pragma unroll
                    for (int cq = 0; cq < 4; cq++) {
                        float pre = wB[cq];
                        #pragma unroll
                        for (int j = 0; j < INT_DIM; j++) pre += pj[j] * wIW[j][cq];
                        ws[cq] += al * lrelu(pre);
                    }
                }
            }
            #pragma unroll
            for (int cq = 0; cq < 4; cq++) sWsum[r * D + 4 * lane + cq] = ws[cq];
        }
        __syncthreads();

        // ---- split wsum into A image; WvProj already landing in BHI ----
        for (int i = tid; i < R1 * D; i += NT1) {
            int r = i >> 7, d = i & 127;
            float v = sWsum[i];
            __half h = __float2half_rn(v);
            uint32_t off = (uint32_t)r * ASTR + (uint32_t)d * 2;
            *(__half*)(smc + BY_AHI + off) = h;
            *(__half*)(smc + BY_ALO + off) = __float2half_rn(v - __half2float(h));
        }
        CP_WAIT0();      // WvProj complete
        __syncthreads();

        // ---- attn_vec = tanh(wsum @ WvProj + projB) (warps 0-7, B=BHI) ----
        if (wid < 8) {
            float c[2][2][4];
            #pragma unroll
            for (int mi = 0; mi < 2; mi++)
            #pragma unroll
            for (int ni = 0; ni < 2; ni++)
            #pragma unroll
            for (int j = 0; j < 4; j++) c[mi][ni][j] = 0.f;

            #pragma unroll
            for (int kk = 0; kk < 8; kk++) {
                const uint32_t ko = kk * 32;
                uint32_t ah[2][4], al[2][4], bh[4];
                LDSM_X4(ah[0][0], ah[0][1], ah[0][2], ah[0][3], aQ0 + ko);
                LDSM_X4(ah[1][0], ah[1][1], ah[1][2], ah[1][3], aQ1 + ko);
                LDSM_X4(al[0][0], al[0][1], al[0][2], al[0][3], aQl0 + ko);
                LDSM_X4(al[1][0], al[1][1], al[1][2], al[1][3], aQl1 + ko);
                LDSM_X4(bh[0], bh[1], bh[2], bh[3], bQ0 + ko);
                #pragma unroll
                for (int mi = 0; mi < 2; mi++)
                #pragma unroll
                for (int ni = 0; ni < 2; ni++) {
                    mma_f16(c[mi][ni], ah[mi], &bh[ni * 2]);
                    mma_f16(c[mi][ni], al[mi], &bh[ni * 2]);
                }
            }
            #pragma unroll
            for (int mi = 0; mi < 2; mi++)
            #pragma unroll
            for (int ci = 0; ci < 2; ci++) {
                int row = 16 * mi + 8 * ci + (lane >> 2);
                size_t base = (size_t)(b0 + row) * 256 + 128;
                #pragma unroll
                for (int ni = 0; ni < 2; ni++) {
                    int col = 16 * wc + 8 * ni + 2 * (lane & 3);
                    float t0 = tanhf(c[mi][ni][2 * ci]     + projB[col]);
                    float t1 = tanhf(c[mi][ni][2 * ci + 1] + projB[col + 1]);
                    __half h0 = __float2half_rn(t0);
                    __half h1 = __float2half_rn(t1);
                    g_xh[base + col]     = h0;
                    g_xl[base + col]     = __float2half_rn(t0 - __half2float(h0));
                    g_xh[base + col + 1] = h1;
                    g_xl[base + col + 1] = __float2half_rn(t1 - __half2float(h1));
                }
            }
        }
        __syncthreads();   // BHI reads done before next tile's Wq prefetch

        if (tile + gridDim.x < NTILES) {   // prefetch Wq for next tile
            for (int i = tid; i < 2176; i += NT1)
                CP_ASYNC16(smb + BY_BHI + (uint32_t)i * 16, (const void*)(((const uint4*)gWqF) + i));
            CP_COMMIT();
        }
    }
}

// =====================================================================
// Kernel 2: MLP (unchanged from R16)
// =====================================================================
__global__ void __launch_bounds__(NT2, 1)
k_mlp(const float* __restrict__ b1, const float* __restrict__ b2,
      const float* __restrict__ Wo, const float* __restrict__ bo,
      float* __restrict__ out)
{
    extern __shared__ float sm[];
    char* smc = (char*)sm;
    const uint32_t smb = smem_u32(sm);

    const int tid  = threadIdx.x;
    const int wid  = tid >> 5;
    const int lane = tid & 31;
    const int b0   = blockIdx.x * R2;
    const int wr = wid >> 3, wc = wid & 7;
    const int lt = lane >> 3, lw = lane & 7;

    auto stageW = [&](int li) {
        const uint4* WF = (const uint4*)((li >= 4) ? gW2F[li & 3] : gW1F[li & 3]);
        uint32_t dstb = smb + M_W0 + (uint32_t)(li & 1) * WBUF;
        for (int i = tid; i < 2304; i += NT2)
            CP_ASYNC16(dstb + (uint32_t)i * 16, (const void*)(WF + i));
        CP_COMMIT();
    };

    stageW(0);

    for (int i = tid; i < 128 * 32; i += NT2) {
        int row = i >> 5, q = i & 31;
        int ch = q >> 3, qq = q & 7;
        size_t src = (size_t)(b0 + row) * 32 + q;
        uint32_t dst = (uint32_t)(ch * XCH + row * XSTRB + qq * 16);
        *(uint4*)(smc + M_XH + dst) = ((const uint4*)g_xh)[src];
        *(uint4*)(smc + M_XL + dst) = ((const uint4*)g_xl)[src];
    }
    CP_WAIT0();
    __syncthreads();

    const uint32_t aoff = (uint32_t)(((lt & 1) * 8 + lw) * XSTRB + (lt >> 1) * 16);
    const uint32_t boff = (uint32_t)((32 * wc + (lt >> 1) * 8 + lw) * XSTRB + (lt & 1) * 16);

    for (int layer = 0; layer < 2; layer++) {
        const float* bias = layer ? b2 : b1;

        float c[4][4][4];
        #pragma unroll
        for (int mi = 0; mi < 4; mi++)
        #pragma unroll
        for (int ni = 0; ni < 4; ni++)
        #pragma unroll
        for (int j = 0; j < 4; j++) c[mi][ni][j] = 0.f;

        for (int kk = 0; kk < 4; kk++) {
            const int li = layer * 4 + kk;
            if (li < 7) stageW(li + 1);

            const uint32_t bB0 = smb + M_W0 + (uint32_t)(li & 1) * WBUF + boff;
            const uint32_t bB1 = bB0 + 16 * XSTRB;
            const uint32_t aChunk = smb + M_XH + (uint32_t)(kk * XCH)
                                  + (uint32_t)(64 * wr) * XSTRB + aoff;
            #pragma unroll
            for (int ks = 0; ks < 4; ks++) {
                const uint32_t ko = ks * 32;
                uint32_t af[4][4], bh[2][4];
                #pragma unroll
                for (int m = 0; m < 4; m++)
                    LDSM_X4(af[m][0], af[m][1], af[m][2], af[m][3],
                            aChunk + (uint32_t)(16 * m) * XSTRB + ko);
                LDSM_X4(bh[0][0], bh[0][1], bh[0][2], bh[0][3], bB0 + ko);
                LDSM_X4(bh[1][0], bh[1][1], bh[1][2], bh[1][3], bB1 + ko);

                #pragma unroll
                for (int mi = 0; mi < 4; mi++)
                #pragma unroll
                for (int ni = 0; ni < 4; ni++)
                    mma_f16(c[mi][ni], af[mi], &bh[ni >> 1][(ni & 1) * 2]);

                #pragma unroll
                for (int m = 0; m < 4; m++)
                    LDSM_X4(af[m][0], af[m][1], af[m][2], af[m][3],
                            aChunk + (M_XL - M_XH) + (uint32_t)(16 * m) * XSTRB + ko);
                #pragma unroll
                for (int mi = 0; mi < 4; mi++)
                #pragma unroll
                for (int ni = 0; ni < 4; ni++)
                    mma_f16(c[mi][ni], af[mi], &bh[ni >> 1][(ni & 1) * 2]);
            }
            CP_WAIT0();
            __syncthreads();
        }

        const int chn = wc >> 1;
        #pragma unroll
        for (int mi = 0; mi < 4; mi++)
        #pragma unroll
        for (int ci = 0; ci < 2; ci++) {
            int row = 64 * wr + 16 * mi + 8 * ci + (lane >> 2);
            #pragma unroll
            for (int ni = 0; ni < 4; ni++) {
                int col = 32 * wc + 8 * ni + 2 * (lane & 3);
                int colin = (wc & 1) * 32 + 8 * ni + 2 * (lane & 3);
                float x0 = lrelu(c[mi][ni][2 * ci]     + bias[col]);
                float x1 = lrelu(c[mi][ni][2 * ci + 1] + bias[col + 1]);
                float h0 = __half2float(__float2half_rn(x0));
                float h1 = __half2float(__float2half_rn(x1));
                uint32_t off = (uint32_t)(chn * XCH + row * XSTRB + colin * 2);
                *(uint32_t*)(smc + M_XH + off) = f16pair(h0, h1);
                *(uint32_t*)(smc + M_XL + off) = f16pair(x0 - h0, x1 - h1);
            }
        }
        __syncthreads();
    }

    {
        float bo0 = bo[0], bo1 = bo[1];
        const int chn = lane >> 3;
        const int colin0 = (lane & 7) * 8;
        #pragma unroll
        for (int rr = 0; rr < 8; rr++) {
            int r = wid * 8 + rr;
            uint32_t off = (uint32_t)(chn * XCH + r * XSTRB + colin0 * 2);
            float a0 = 0.f, a1 = 0.f;
            #pragma unroll
            for (int kp = 0; kp < 4; kp++) {
                uint32_t uh = *(const uint32_t*)(smc + M_XH + off + kp * 4);
                uint32_t ul = *(const uint32_t*)(smc + M_XL + off + kp * 4);
                __half2 vh = *(__half2*)&uh;
                __half2 vl = *(__half2*)&ul;
                float x0 = __half2float(vh.x) + __half2float(vl.x);
                float x1 = __half2float(vh.y) + __half2float(vl.y);
                int col = lane * 8 + 2 * kp;
                float2 w0 = ((const float2*)Wo)[col];
                float2 w1 = ((const float2*)Wo)[col + 1];
                a0 += x0 * w0.x + x1 * w1.x;
                a1 += x0 * w0.y + x1 * w1.y;
            }
            #pragma unroll
            for (int o = 16; o > 0; o >>= 1) {
                a0 += __shfl_xor_sync(0xffffffffu, a0, o);
                a1 += __shfl_xor_sync(0xffffffffu, a1, o);
            }
            if (lane == 0) {
                out[(size_t)(b0 + r) * 2 + 0] = a0 + bo0;
                out[(size_t)(b0 + r) * 2 + 1] = a1 + bo1;
            }
        }
    }
}

extern "C" void kernel_launch(void* const* d_in, const int* in_sizes, int n_in,
                              void* d_out, int out_size)
{
    const float* obs   = (const float*)d_in[0];
    const float* ownW  = (const float*)d_in[1];
    const float* ownB  = (const float*)d_in[2];
    const float* intW  = (const float*)d_in[3];
    const float* intB  = (const float*)d_in[4];
    const float* Wq    = (const float*)d_in[5];
    const float* Wk    = (const float*)d_in[6];
    const float* Wv    = (const float*)d_in[7];
    const float* vatt  = (const float*)d_in[8];
    const float* projW = (const float*)d_in[9];
    const float* projB = (const float*)d_in[10];
    const float* W1    = (const float*)d_in[11];
    const float* b1    = (const float*)d_in[12];
    const float* W2    = (const float*)d_in[13];
    const float* b2    = (const float*)d_in[14];
    const float* Wo    = (const float*)d_in[15];
    const float* bo    = (const float*)d_in[16];
    float* out = (float*)d_out;

    int dev = 0, nsm = 148;
    cudaGetDevice(&dev);
    cudaDeviceGetAttribute(&nsm, cudaDevAttrMultiProcessorCount, dev);

    cudaFuncSetAttribute(k_attn, cudaFuncAttributeMaxDynamicSharedMemorySize, SMEM1_BYTES);
    cudaFuncSetAttribute(k_mlp,  cudaFuncAttributeMaxDynamicSharedMemorySize, SMEM2_BYTES);

    k_prep<<<352, 256>>>(Wk, W1, W2, Wq, Wv, projW);
    k_attn<<<nsm, NT1, SMEM1_BYTES>>>(obs, ownW, ownB, intW, intB, vatt, projB);
    k_mlp<<<B_TOT / R2, NT2, SMEM2_BYTES>>>(b1, b2, Wo, bo, out);
}